// round 9
// baseline (speedup 1.0000x reference)
#include <cuda_runtime.h>
#include <cstdint>

// Per-batch least squares: A = [-x1,-x2,-x3, 1] (32x4), r = x0 (32),
// out = (A^T A)^{-1} A^T r  (4 values per batch).
//
// HBM-bound streaming kernel. Strategy:
//  - Persistent block per SM; 6-stage cp.async.bulk (TMA bulk) pipeline,
//    32KB (64 batches) per stage -> up to 160KB of DRAM reads in flight
//    per SM, independent of register file / occupancy.
//  - Compute: 8 lanes per batch, 64 batches per 512-thread block pass.
//    Lane l of group g reads rows l, l+8, l+16, l+24 from SMEM: each
//    8-lane LDS.128 phase reads one contiguous 128B line -> conflict-free.
//  - 13 sums reduced with 3 butterfly shfls each (xor 1,2,4), then a tiny
//    unrolled SPD 4x4 solve; group leader writes a float4 (coalesced).

#define THREADS      512
#define NSTAGES      6
#define CHUNK_B      64                        // batches per chunk
#define CHUNK_BYTES  (CHUNK_B * 512)           // 32768
#define SMEM_STAGES  (NSTAGES * CHUNK_BYTES)   // 196608
#define SMEM_TOTAL   (SMEM_STAGES + 64)        // + mbarriers

__device__ __forceinline__ uint32_t s2u(const void* p) {
    uint32_t a;
    asm("{ .reg .u64 t; cvta.to.shared.u64 t, %1; cvt.u32.u64 %0, t; }"
        : "=r"(a) : "l"(p));
    return a;
}

__device__ __forceinline__ void mbar_init(uint32_t mbar, uint32_t count) {
    asm volatile("mbarrier.init.shared.b64 [%0], %1;" :: "r"(mbar), "r"(count) : "memory");
}

__device__ __forceinline__ void mbar_expect_tx(uint32_t mbar, uint32_t bytes) {
    asm volatile("mbarrier.arrive.expect_tx.shared.b64 _, [%0], %1;"
                 :: "r"(mbar), "r"(bytes) : "memory");
}

__device__ __forceinline__ void mbar_wait(uint32_t mbar, uint32_t parity) {
    asm volatile(
        "{\n\t"
        ".reg .pred P;\n\t"
        "WAIT_%=:\n\t"
        "mbarrier.try_wait.parity.acquire.cta.shared::cta.b64 P, [%0], %1, 0x989680;\n\t"
        "@P bra DONE_%=;\n\t"
        "bra WAIT_%=;\n\t"
        "DONE_%=:\n\t"
        "}"
        :: "r"(mbar), "r"(parity) : "memory");
}

__device__ __forceinline__ void bulk_copy_g2s(uint32_t dst_smem, const void* src,
                                              uint32_t bytes, uint32_t mbar) {
    asm volatile(
        "cp.async.bulk.shared::cluster.global.mbarrier::complete_tx::bytes "
        "[%0], [%1], %2, [%3];"
        :: "r"(dst_smem), "l"(src), "r"(bytes), "r"(mbar) : "memory");
}

__global__ void __launch_bounds__(THREADS, 1)
basicls_pipe(const float* __restrict__ x, float4* __restrict__ out, int nbatch) {
    extern __shared__ __align__(1024) unsigned char smem[];
    const uint32_t sbase = s2u(smem);
    const uint32_t mbar0 = sbase + SMEM_STAGES;

    const int tid = threadIdx.x;
    const int g   = tid >> 3;   // group (batch within chunk): 0..63
    const int l   = tid & 7;    // lane within group: 0..7

    const int nchunks = (nbatch + CHUNK_B - 1) / CHUNK_B;

    if (tid == 0) {
#pragma unroll
        for (int s = 0; s < NSTAGES; s++) mbar_init(mbar0 + s * 8, 1);
    }
    __syncthreads();

    // chunks handled by this block: blockIdx.x, +gridDim.x, ...
    const int total_i = (blockIdx.x < nchunks)
                        ? ((nchunks - 1 - blockIdx.x) / gridDim.x + 1) : 0;

    // Prologue: prefetch up to NSTAGES chunks
    if (tid == 0) {
        const int pre = (total_i < NSTAGES) ? total_i : NSTAGES;
        for (int s = 0; s < pre; s++) {
            const int c = blockIdx.x + s * gridDim.x;
            int nb = nbatch - c * CHUNK_B;
            if (nb > CHUNK_B) nb = CHUNK_B;
            const uint32_t bytes = (uint32_t)nb * 512u;
            mbar_expect_tx(mbar0 + s * 8, bytes);
            bulk_copy_g2s(sbase + s * CHUNK_BYTES,
                          x + (long long)c * (CHUNK_B * 128), bytes, mbar0 + s * 8);
        }
    }

    for (int i = 0; i < total_i; i++) {
        const int stage  = i % NSTAGES;
        const int parity = (i / NSTAGES) & 1;
        const int c      = blockIdx.x + i * gridDim.x;

        mbar_wait(mbar0 + stage * 8, parity);

        // ---- compute 64 batches from SMEM stage ----
        const float4* __restrict__ sb =
            (const float4*)(smem + stage * CHUNK_BYTES) + g * 32;

        float S0 = 0.f, S1 = 0.f, S2 = 0.f, S3 = 0.f;
        float S11 = 0.f, S12 = 0.f, S13 = 0.f;
        float S22 = 0.f, S23 = 0.f, S33 = 0.f;
        float S01 = 0.f, S02 = 0.f, S03 = 0.f;

#pragma unroll
        for (int k = 0; k < 4; k++) {
            const float4 v = sb[8 * k + l];   // rows l, l+8, l+16, l+24
            const float x0 = v.x, x1 = v.y, x2 = v.z, x3 = v.w;
            S0  += x0;      S1  += x1;      S2  += x2;      S3  += x3;
            S11 += x1 * x1; S12 += x1 * x2; S13 += x1 * x3;
            S22 += x2 * x2; S23 += x2 * x3; S33 += x3 * x3;
            S01 += x0 * x1; S02 += x0 * x2; S03 += x0 * x3;
        }

        // reduce within each 8-lane group (3 butterfly steps)
#define RED8(s)                                        \
        s += __shfl_xor_sync(0xffffffffu, s, 1);       \
        s += __shfl_xor_sync(0xffffffffu, s, 2);       \
        s += __shfl_xor_sync(0xffffffffu, s, 4);

        RED8(S0)  RED8(S1)  RED8(S2)  RED8(S3)
        RED8(S11) RED8(S12) RED8(S13)
        RED8(S22) RED8(S23) RED8(S33)
        RED8(S01) RED8(S02) RED8(S03)
#undef RED8

        // Normal equations G y = b ; A cols: c0=-x1, c1=-x2, c2=-x3, c3=1
        float G[4][4], b[4];
        G[0][0] = S11;  G[0][1] = S12;  G[0][2] = S13;  G[0][3] = -S1;
        G[1][0] = S12;  G[1][1] = S22;  G[1][2] = S23;  G[1][3] = -S2;
        G[2][0] = S13;  G[2][1] = S23;  G[2][2] = S33;  G[2][3] = -S3;
        G[3][0] = -S1;  G[3][1] = -S2;  G[3][2] = -S3;  G[3][3] = 32.0f;
        b[0] = -S01; b[1] = -S02; b[2] = -S03; b[3] = S0;

#pragma unroll
        for (int p = 0; p < 4; p++) {
            const float inv = __frcp_rn(G[p][p]);
#pragma unroll
            for (int j = 0; j < 4; j++) {
                if (j > p) {
                    const float f = G[j][p] * inv;
#pragma unroll
                    for (int k = 0; k < 4; k++)
                        if (k >= p) G[j][k] -= f * G[p][k];
                    b[j] -= f * b[p];
                }
            }
        }
        const float y3 = b[3] / G[3][3];
        const float y2 = (b[2] - G[2][3] * y3) / G[2][2];
        const float y1 = (b[1] - G[1][2] * y2 - G[1][3] * y3) / G[1][1];
        const float y0 = (b[0] - G[0][1] * y1 - G[0][2] * y2 - G[0][3] * y3) / G[0][0];

        const int batch = c * CHUNK_B + g;
        if (l == 0 && batch < nbatch)
            out[batch] = make_float4(y0, y1, y2, y3);

        __syncthreads();   // all readers done with this stage

        // reissue this stage for chunk i + NSTAGES
        if (tid == 0) {
            const int nxt = i + NSTAGES;
            if (nxt < total_i) {
                const int cn = blockIdx.x + nxt * gridDim.x;
                int nb = nbatch - cn * CHUNK_B;
                if (nb > CHUNK_B) nb = CHUNK_B;
                const uint32_t bytes = (uint32_t)nb * 512u;
                mbar_expect_tx(mbar0 + stage * 8, bytes);
                bulk_copy_g2s(sbase + stage * CHUNK_BYTES,
                              x + (long long)cn * (CHUNK_B * 128), bytes,
                              mbar0 + stage * 8);
            }
        }
    }
}

extern "C" void kernel_launch(void* const* d_in, const int* in_sizes, int n_in,
                              void* d_out, int out_size) {
    const float* x = (const float*)d_in[0];   // (B, 32, 4) float32
    // d_in[1] = pad_mask — unused by the reference computation
    float4* out = (float4*)d_out;             // (B, 4) float32

    const int nbatch  = in_sizes[0] / 128;    // elements / (32*4)
    const int nchunks = (nbatch + CHUNK_B - 1) / CHUNK_B;

    int nsm = 148;
    cudaDeviceGetAttribute(&nsm, cudaDevAttrMultiProcessorCount, 0);
    int grid = (nchunks < nsm) ? nchunks : nsm;

    cudaFuncSetAttribute(basicls_pipe,
                         cudaFuncAttributeMaxDynamicSharedMemorySize, SMEM_TOTAL);
    basicls_pipe<<<grid, THREADS, SMEM_TOTAL>>>(x, out, nbatch);
}